// round 9
// baseline (speedup 1.0000x reference)
#include <cuda_runtime.h>
#include <cuda_bf16.h>
#include <cuda_fp16.h>
#include <stdint.h>

// Problem dims
#define NB   2048
#define NT   64
#define NC   384
#define NHN  6
#define NHS  64
#define MTOK (NB*NT)      // 131072 tokens
#define F3   (3*NC)       // 1152

// ---------------- workspaces (static device memory: allowed) ----------------
__device__ __half g_Xhi[MTOK * NC];
__device__ __half g_Xlo[MTOK * NC];
__device__ __half g_Wqh[F3 * NC];        // weights: fp16 hi only
__device__ __half g_Wph[NC * NC];
__device__ float  g_qkv[MTOK * F3];      // 604MB fp32 qkv
__device__ __half g_Ahi[MTOK * NC];      // attention output hi (fp16)
__device__ __half g_Alo[MTOK * NC];      // attention output lo (fp16)

// ---------------- helpers ----------------
__device__ __forceinline__ uint32_t smem_u32(const void* p) {
    return (uint32_t)__cvta_generic_to_shared(p);
}
__device__ __forceinline__ void ldsm_x4(uint32_t* r, uint32_t addr) {
    asm volatile("ldmatrix.sync.aligned.m8n8.x4.shared.b16 {%0,%1,%2,%3}, [%4];\n"
        : "=r"(r[0]), "=r"(r[1]), "=r"(r[2]), "=r"(r[3]) : "r"(addr));
}
__device__ __forceinline__ void ldsm_x2(uint32_t* r, uint32_t addr) {
    asm volatile("ldmatrix.sync.aligned.m8n8.x2.shared.b16 {%0,%1}, [%2];\n"
        : "=r"(r[0]), "=r"(r[1]) : "r"(addr));
}
__device__ __forceinline__ void mma_bf16(float* c, const uint32_t* a, const uint32_t* b) {
    asm volatile("mma.sync.aligned.m16n8k16.row.col.f32.bf16.bf16.f32 "
        "{%0,%1,%2,%3}, {%4,%5,%6,%7}, {%8,%9}, {%0,%1,%2,%3};\n"
        : "+f"(c[0]), "+f"(c[1]), "+f"(c[2]), "+f"(c[3])
        : "r"(a[0]), "r"(a[1]), "r"(a[2]), "r"(a[3]), "r"(b[0]), "r"(b[1]));
}
__device__ __forceinline__ void mma_f16(float* c, const uint32_t* a, const uint32_t* b) {
    asm volatile("mma.sync.aligned.m16n8k16.row.col.f32.f16.f16.f32 "
        "{%0,%1,%2,%3}, {%4,%5,%6,%7}, {%8,%9}, {%0,%1,%2,%3};\n"
        : "+f"(c[0]), "+f"(c[1]), "+f"(c[2]), "+f"(c[3])
        : "r"(a[0]), "r"(a[1]), "r"(a[2]), "r"(a[3]), "r"(b[0]), "r"(b[1]));
}
__device__ __forceinline__ void cp16(uint32_t dst, const void* src) {
    asm volatile("cp.async.cg.shared.global [%0], [%1], 16;\n" :: "r"(dst), "l"(src));
}
__device__ __forceinline__ void cp_commit() {
    asm volatile("cp.async.commit_group;\n" ::: "memory");
}
// bf16 hi/lo pack (used inside attention math)
__device__ __forceinline__ void pack_hilo(float a, float b, uint32_t& h, uint32_t& l) {
    __nv_bfloat16 ha = __float2bfloat16(a), hb = __float2bfloat16(b);
    __nv_bfloat162 H; H.x = ha; H.y = hb; h = *(uint32_t*)&H;
    __nv_bfloat162 L;
    L.x = __float2bfloat16(a - __bfloat162float(ha));
    L.y = __float2bfloat16(b - __bfloat162float(hb));
    l = *(uint32_t*)&L;
}
// fp16 hi/lo pack (GEMM operand precision)
__device__ __forceinline__ void pack_hilo_h(float a, float b, uint32_t& h, uint32_t& l) {
    __half ha = __float2half_rn(a), hb = __float2half_rn(b);
    __half2 H; H.x = ha; H.y = hb; h = *(uint32_t*)&H;
    __half2 L;
    L.x = __float2half_rn(a - __half2float(ha));
    L.y = __float2half_rn(b - __half2float(hb));
    l = *(uint32_t*)&L;
}

// ---------------- fp32 -> fp16 hi/lo split (activations) ----------------
__global__ void split2h_kernel(const float* __restrict__ in,
                               __half* __restrict__ hi,
                               __half* __restrict__ lo, int n4) {
    int i = blockIdx.x * blockDim.x + threadIdx.x;
    if (i >= n4) return;
    float4 v = ((const float4*)in)[i];
    uint2 hv, lv;
    pack_hilo_h(v.x, v.y, hv.x, lv.x);
    pack_hilo_h(v.z, v.w, hv.y, lv.y);
    *(uint2*)&hi[4 * i] = hv;
    *(uint2*)&lo[4 * i] = lv;
}

// ---------------- fp32 -> fp16 hi split (weights) ----------------
__global__ void split1h_kernel(const float* __restrict__ in,
                               __half* __restrict__ hi, int n4) {
    int i = blockIdx.x * blockDim.x + threadIdx.x;
    if (i >= n4) return;
    float4 v = ((const float4*)in)[i];
    __half2 H0, H1;
    H0.x = __float2half_rn(v.x); H0.y = __float2half_rn(v.y);
    H1.x = __float2half_rn(v.z); H1.y = __float2half_rn(v.w);
    uint2 hv; hv.x = *(uint32_t*)&H0; hv.y = *(uint32_t*)&H1;
    *(uint2*)&hi[4 * i] = hv;
}

// ---------------- fp16 2-MMA split GEMM, 3-stage cp.async, 1 sync/iter ----------------
// C[M,N] = A[M,K] * B[N,K]^T (+bias);  A = Ah+Al (fp16x2), B = Bh (fp16)
#define BM 128
#define BN 128
#define BK 32
#define SST 40         // smem row stride (half elems): 32 + 8 pad
#define NSTAGE 3
// dynamic smem layout (halfs): A[stage][part][BM][SST] then B[stage][BN][SST]
#define SM_A_HALFS (NSTAGE * 2 * BM * SST)
#define SM_B_HALFS (NSTAGE * BN * SST)
#define GM_SMEM_BYTES ((SM_A_HALFS + SM_B_HALFS) * 2)   // 92160

__global__ __launch_bounds__(256, 2)
void gemm_fp16x2(const __half* __restrict__ Ahi,
                 const __half* __restrict__ Alo,
                 const __half* __restrict__ Bh,
                 float* __restrict__ C,
                 const float* __restrict__ bias,
                 int Kdim, int Ndim)
{
    extern __shared__ __half dsm[];
    __half* sA = dsm;                 // [(stage*2+part)*BM + row]*SST + col
    __half* sB = dsm + SM_A_HALFS;    // [stage*BN + row]*SST + col

    const int tid  = threadIdx.x;
    const int lane = tid & 31;
    const int warp = tid >> 5;
    const int warpM = warp >> 2;   // 0..1  -> 64 rows each
    const int warpN = warp & 3;    // 0..3  -> 32 cols each

    const int lr = tid >> 2;          // 0..63
    const int lc = (tid & 3) << 3;    // 0,8,16,24 half elems (16B)

    const size_t aBase = (size_t)blockIdx.y * BM * Kdim;
    const size_t bBase = (size_t)blockIdx.x * BN * Kdim;

    const int nk = Kdim / BK;   // 12

    float acc[4][4][4];
    #pragma unroll
    for (int mi = 0; mi < 4; mi++)
        #pragma unroll
        for (int ni = 0; ni < 4; ni++)
            #pragma unroll
            for (int q = 0; q < 4; q++) acc[mi][ni][q] = 0.f;

    auto load_tile = [&](int it) {
        const int st = it % NSTAGE;
        const int kt = it * BK;
        #pragma unroll
        for (int p = 0; p < 2; p++) {
            int r = lr + 64 * p;
            size_t goff = (size_t)r * Kdim + kt + lc;
            cp16(smem_u32(&sA[((st * 2 + 0) * BM + r) * SST + lc]), Ahi + aBase + goff);
            cp16(smem_u32(&sA[((st * 2 + 1) * BM + r) * SST + lc]), Alo + aBase + goff);
            cp16(smem_u32(&sB[(st * BN + r) * SST + lc]), Bh + bBase + goff);
        }
        cp_commit();
    };

    load_tile(0);
    load_tile(1);

    for (int it = 0; it < nk; it++) {
        // ensure load(it) landed: allow 1 newer group in flight (tail: 0)
        if (it + 1 < nk) {
            asm volatile("cp.async.wait_group 1;\n" ::: "memory");
        } else {
            asm volatile("cp.async.wait_group 0;\n" ::: "memory");
        }
        __syncthreads();
        // prefetch 2 ahead AFTER the barrier: target buf (it+2)%3 == (it-1)%3,
        // whose readers (compute(it-1)) all finished before this barrier.
        if (it + 2 < nk) load_tile(it + 2);

        const int buf = it % NSTAGE;
        #pragma unroll
        for (int kk = 0; kk < 2; kk++) {
            uint32_t ah[4][4], al[4][4], bh[4][2];
            const int arow = warpM * 64 + (lane & 15);
            const int acol = kk * 16 + ((lane >> 4) << 3);
            #pragma unroll
            for (int mi = 0; mi < 4; mi++) {
                ldsm_x4(ah[mi], smem_u32(&sA[((buf * 2 + 0) * BM + arow + mi * 16) * SST + acol]));
                ldsm_x4(al[mi], smem_u32(&sA[((buf * 2 + 1) * BM + arow + mi * 16) * SST + acol]));
            }
            // B: two n-tiles per ldsm_x4 (16 rows x 16 k-cols)
            #pragma unroll
            for (int pr = 0; pr < 2; pr++) {
                uint32_t r4[4];
                const int brow = warpN * 32 + pr * 16 + (lane & 15);
                const int bcol = kk * 16 + ((lane >> 4) << 3);
                ldsm_x4(r4, smem_u32(&sB[(buf * BN + brow) * SST + bcol]));
                bh[2 * pr + 0][0] = r4[0]; bh[2 * pr + 0][1] = r4[2];
                bh[2 * pr + 1][0] = r4[1]; bh[2 * pr + 1][1] = r4[3];
            }
            #pragma unroll
            for (int mi = 0; mi < 4; mi++)
                #pragma unroll
                for (int ni = 0; ni < 4; ni++) {
                    mma_f16(acc[mi][ni], ah[mi], bh[ni]);  // Ah*Bh
                    mma_f16(acc[mi][ni], al[mi], bh[ni]);  // Al*Bh
                }
        }
    }

    // epilogue
    #pragma unroll
    for (int mi = 0; mi < 4; mi++) {
        int r = blockIdx.y * BM + warpM * 64 + mi * 16 + (lane >> 2);
        #pragma unroll
        for (int ni = 0; ni < 4; ni++) {
            int c = blockIdx.x * BN + warpN * 32 + ni * 8 + (lane & 3) * 2;
            float bb0 = 0.f, bb1 = 0.f;
            if (bias) { bb0 = bias[c]; bb1 = bias[c + 1]; }
            float2 v0; v0.x = acc[mi][ni][0] + bb0; v0.y = acc[mi][ni][1] + bb1;
            float2 v1; v1.x = acc[mi][ni][2] + bb0; v1.y = acc[mi][ni][3] + bb1;
            *(float2*)&C[(size_t)r * Ndim + c]       = v0;
            *(float2*)&C[(size_t)(r + 8) * Ndim + c] = v1;
        }
    }
}

// ---------------- tensor-core causal attention per (b,h), bf16x3 split ----------------
// smem (bf16, row stride AS=72): Qh,Ql [t][d]; Kh,Kl [s][d]; VTh,VTl [d][s]
// O staging (fp32 [64][68]) overlays Kh/Kl after S is computed.
#define AS 72
#define ATTN_SMEM (6 * 64 * AS * 2)   // 55296 bytes

__global__ __launch_bounds__(128)
void attn_tc_kernel(const float* __restrict__ qkv,
                    __half* __restrict__ Ohi,
                    __half* __restrict__ Olo)
{
    extern __shared__ __nv_bfloat16 sb[];
    __nv_bfloat16* sQh = sb;
    __nv_bfloat16* sQl = sb + 64 * AS;
    __nv_bfloat16* sKh = sb + 2 * 64 * AS;
    __nv_bfloat16* sKl = sb + 3 * 64 * AS;
    __nv_bfloat16* sVh = sb + 4 * 64 * AS;   // transposed: [d][s]
    __nv_bfloat16* sVl = sb + 5 * 64 * AS;
    float* sO = (float*)(sb + 2 * 64 * AS);  // overlays Kh/Kl (17408B <= 18432B)

    const int bh = blockIdx.x;
    const int b = bh / NHN, h = bh % NHN;
    const int tid = threadIdx.x;
    const int lane = tid & 31;
    const int warp = tid >> 5;
    const size_t base = (size_t)b * NT * F3;
    const int offq = h * NHS, offk = NC + h * NHS, offv = 2 * NC + h * NHS;

    // ---- load qkv fp32, convert to bf16 hi/lo ----
    for (int i = tid; i < 64 * 16; i += 128) {
        int t = i >> 4, j = i & 15;
        const float* row = qkv + base + (size_t)t * F3;
        float4 q = *(const float4*)(row + offq + 4 * j);
        uint2 hv, lv;
        pack_hilo(q.x, q.y, hv.x, lv.x);
        pack_hilo(q.z, q.w, hv.y, lv.y);
        *(uint2*)&sQh[t * AS + 4 * j] = hv;
        *(uint2*)&sQl[t * AS + 4 * j] = lv;
        float4 k = *(const float4*)(row + offk + 4 * j);
        pack_hilo(k.x, k.y, hv.x, lv.x);
        pack_hilo(k.z, k.w, hv.y, lv.y);
        *(uint2*)&sKh[t * AS + 4 * j] = hv;
        *(uint2*)&sKl[t * AS + 4 * j] = lv;
        float4 v = *(const float4*)(row + offv + 4 * j);
        float vv[4] = {v.x, v.y, v.z, v.w};
        #pragma unroll
        for (int dd = 0; dd < 4; dd++) {
            __nv_bfloat16 hb = __float2bfloat16(vv[dd]);
            sVh[(4 * j + dd) * AS + t] = hb;
            sVl[(4 * j + dd) * AS + t] = __float2bfloat16(vv[dd] - __bfloat162float(hb));
        }
    }
    __syncthreads();

    // ---- S = Q @ K^T (per warp: rows m0..m0+15, all 64 cols) ----
    const int m0 = warp * 16;
    float accS[8][4];
    #pragma unroll
    for (int j = 0; j < 8; j++)
        #pragma unroll
        for (int q = 0; q < 4; q++) accS[j][q] = 0.f;

    #pragma unroll
    for (int ks = 0; ks < 4; ks++) {
        uint32_t qh[4], ql[4];
        const int arow = m0 + (lane & 15);
        const int acol = ks * 16 + ((lane >> 4) << 3);
        ldsm_x4(qh, smem_u32(&sQh[arow * AS + acol]));
        ldsm_x4(ql, smem_u32(&sQl[arow * AS + acol]));
        const int brow0 = lane & 7;
        const int bcol = ks * 16 + ((lane >> 3) & 1) * 8;
        #pragma unroll
        for (int j = 0; j < 8; j++) {
            uint32_t kh[2], kl[2];
            ldsm_x2(kh, smem_u32(&sKh[(j * 8 + brow0) * AS + bcol]));
            ldsm_x2(kl, smem_u32(&sKl[(j * 8 + brow0) * AS + bcol]));
            mma_bf16(accS[j], qh, kh);
            mma_bf16(accS[j], qh, kl);
            mma_bf16(accS[j], ql, kh);
        }
    }

    // ---- causal softmax in registers ----
    const int r0 = m0 + (lane >> 2);
    const int r8 = r0 + 8;
    const float scale = 0.125f;
    float mx0 = -1e30f, mx1 = -1e30f;
    #pragma unroll
    for (int j = 0; j < 8; j++) {
        int c = j * 8 + (lane & 3) * 2;
        accS[j][0] = (c     <= r0) ? accS[j][0] * scale : -1e30f;
        accS[j][1] = (c + 1 <= r0) ? accS[j][1] * scale : -1e30f;
        accS[j][2] = (c     <= r8) ? accS[j][2] * scale : -1e30f;
        accS[j][3] = (c + 1 <= r8) ? accS[j][3] * scale : -1e30f;
        mx0 = fmaxf(mx0, fmaxf(accS[j][0], accS[j][1]));
        mx1 = fmaxf(mx1, fmaxf(accS[j][2], accS[j][3]));
    }
    mx0 = fmaxf(mx0, __shfl_xor_sync(0xFFFFFFFF, mx0, 1));
    mx0 = fmaxf(mx0, __shfl_xor_sync(0xFFFFFFFF, mx0, 2));
    mx1 = fmaxf(mx1, __shfl_xor_sync(0xFFFFFFFF, mx1, 1));
    mx1 = fmaxf(mx1, __shfl_xor_sync(0xFFFFFFFF, mx1, 2));
    float sum0 = 0.f, sum1 = 0.f;
    #pragma unroll
    for (int j = 0; j < 8; j++) {
        accS[j][0] = __expf(accS[j][0] - mx0);
        accS[j][1] = __expf(accS[j][1] - mx0);
        accS[j][2] = __expf(accS[j][2] - mx1);
        accS[j][3] = __expf(accS[j][3] - mx1);
        sum0 += accS[j][0] + accS[j][1];
        sum1 += accS[j][2] + accS[j][3];
    }
    sum0 += __shfl_xor_sync(0xFFFFFFFF, sum0, 1);
    sum0 += __shfl_xor_sync(0xFFFFFFFF, sum0, 2);
    sum1 += __shfl_xor_sync(0xFFFFFFFF, sum1, 1);
    sum1 += __shfl_xor_sync(0xFFFFFFFF, sum1, 2);
    const float inv0 = 1.f / sum0, inv1 = 1.f / sum1;
    #pragma unroll
    for (int j = 0; j < 8; j++) {
        accS[j][0] *= inv0; accS[j][1] *= inv0;
        accS[j][2] *= inv1; accS[j][3] *= inv1;
    }

    // ---- O = P @ V  (P from C-frag -> A-frag repack, hi/lo split) ----
    float accO[8][4];
    #pragma unroll
    for (int j = 0; j < 8; j++)
        #pragma unroll
        for (int q = 0; q < 4; q++) accO[j][q] = 0.f;

    #pragma unroll
    for (int ks = 0; ks < 4; ks++) {
        const int j0 = 2 * ks, j1 = 2 * ks + 1;
        uint32_t ph[4], pl[4];
        pack_hilo(accS[j0][0], accS[j0][1], ph[0], pl[0]);
        pack_hilo(accS[j0][2], accS[j0][3], ph[1], pl[1]);
        pack_hilo(accS[j1][0], accS[j1][1], ph[2], pl[2]);
        pack_hilo(accS[j1][2], accS[j1][3], ph[3], pl[3]);
        const int brow0 = lane & 7;
        const int bcol = ks * 16 + ((lane >> 3) & 1) * 8;
        #pragma unroll
        for (int n = 0; n < 8; n++) {
            uint32_t vh[2], vl[2];
            ldsm_x2(vh, smem_u32(&sVh[(n * 8 + brow0) * AS + bcol]));
            ldsm_x2(vl, smem_u32(&sVl[(n * 8 + brow0) * AS + bcol]));
            mma_bf16(accO[n], ph, vh);
            mma_bf16(accO[n], ph, vl);
            mma_bf16(accO[n], pl, vh);
        }
    }

    // ---- stage O in smem (overlay on K), then coalesced fp16 hi/lo write ----
    __syncthreads();   // everyone done with sK reads
    #pragma unroll
    for (int j = 0; j < 8; j++) {
        int c = j * 8 + (lane & 3) * 2;
        sO[r0 * 68 + c]     = accO[j][0];
        sO[r0 * 68 + c + 1] = accO[j][1];
        sO[r8 * 68 + c]     = accO[j][2];
        sO[r8 * 68 + c + 1] = accO[j][3];
    }
    __syncthreads();

    for (int i = tid; i < 64 * 16; i += 128) {
        int t = i >> 4, j = i & 15;
        float4 a = *(float4*)&sO[t * 68 + 4 * j];
        uint2 hv, lv;
        pack_hilo_h(a.x, a.y, hv.x, lv.x);
        pack_hilo_h(a.z, a.w, hv.y, lv.y);
        size_t off = (size_t)(b * NT + t) * NC + h * NHS + 4 * j;
        *(uint2*)&Ohi[off] = hv;
        *(uint2*)&Olo[off] = lv;
    }
}

// ---------------- launch ----------------
extern "C" void kernel_launch(void* const* d_in, const int* in_sizes, int n_in,
                              void* d_out, int out_size) {
    const float* x    = (const float*)d_in[0];
    const float* Wqkv = (const float*)d_in[1];
    const float* Wp   = (const float*)d_in[2];
    const float* bp   = (const float*)d_in[3];
    float* out = (float*)d_out;

    void *pXhi, *pXlo, *pWqh, *pWph, *pQkv, *pAhi, *pAlo;
    cudaGetSymbolAddress(&pXhi, g_Xhi);
    cudaGetSymbolAddress(&pXlo, g_Xlo);
    cudaGetSymbolAddress(&pWqh, g_Wqh);
    cudaGetSymbolAddress(&pWph, g_Wph);
    cudaGetSymbolAddress(&pQkv, g_qkv);
    cudaGetSymbolAddress(&pAhi, g_Ahi);
    cudaGetSymbolAddress(&pAlo, g_Alo);

    int n4;
    n4 = MTOK * NC / 4;
    split2h_kernel<<<(n4 + 255) / 256, 256>>>(x, (__half*)pXhi, (__half*)pXlo, n4);
    n4 = F3 * NC / 4;
    split1h_kernel<<<(n4 + 255) / 256, 256>>>(Wqkv, (__half*)pWqh, n4);
    n4 = NC * NC / 4;
    split1h_kernel<<<(n4 + 255) / 256, 256>>>(Wp, (__half*)pWph, n4);

    cudaFuncSetAttribute(gemm_fp16x2, cudaFuncAttributeMaxDynamicSharedMemorySize, GM_SMEM_BYTES);

    // qkv = X @ Wqkv^T : M=131072, N=1152, K=384
    gemm_fp16x2<<<dim3(F3 / BN, MTOK / BM), 256, GM_SMEM_BYTES>>>(
        (const __half*)pXhi, (const __half*)pXlo,
        (const __half*)pWqh,
        (float*)pQkv, nullptr, NC, F3);

    cudaFuncSetAttribute(attn_tc_kernel, cudaFuncAttributeMaxDynamicSharedMemorySize, ATTN_SMEM);
    attn_tc_kernel<<<NB * NHN, 128, ATTN_SMEM>>>(
        (const float*)pQkv, (__half*)pAhi, (__half*)pAlo);

    // out = Attn @ Wp^T + bp : M=131072, N=384, K=384
    gemm_fp16x2<<<dim3(NC / BN, MTOK / BM), 256, GM_SMEM_BYTES>>>(
        (const __half*)pAhi, (const __half*)pAlo,
        (const __half*)pWph,
        out, bp, NC, NC);
}

// round 10
// speedup vs baseline: 1.1102x; 1.1102x over previous
#include <cuda_runtime.h>
#include <cuda_bf16.h>
#include <cuda_fp16.h>
#include <stdint.h>

// Problem dims
#define NB   2048
#define NT   64
#define NC   384
#define NHN  6
#define NHS  64
#define MTOK (NB*NT)      // 131072 tokens
#define F3   (3*NC)       // 1152

// ---------------- workspaces (static device memory: allowed) ----------------
__device__ __half g_Xhi[MTOK * NC];
__device__ __half g_Xlo[MTOK * NC];
__device__ __half g_Wqh[F3 * NC];            // weights: fp16 hi only
__device__ __half g_Wph[NC * NC];
__device__ __nv_bfloat16 g_qkvh[MTOK * F3];  // qkv bf16 hi (302MB)
__device__ __nv_bfloat16 g_qkvl[MTOK * F3];  // qkv bf16 lo (302MB)
__device__ __half g_Ahi[MTOK * NC];          // attention output hi (fp16)
__device__ __half g_Alo[MTOK * NC];          // attention output lo (fp16)

// ---------------- helpers ----------------
__device__ __forceinline__ uint32_t smem_u32(const void* p) {
    return (uint32_t)__cvta_generic_to_shared(p);
}
__device__ __forceinline__ void ldsm_x4(uint32_t* r, uint32_t addr) {
    asm volatile("ldmatrix.sync.aligned.m8n8.x4.shared.b16 {%0,%1,%2,%3}, [%4];\n"
        : "=r"(r[0]), "=r"(r[1]), "=r"(r[2]), "=r"(r[3]) : "r"(addr));
}
__device__ __forceinline__ void ldsm_x2(uint32_t* r, uint32_t addr) {
    asm volatile("ldmatrix.sync.aligned.m8n8.x2.shared.b16 {%0,%1}, [%2];\n"
        : "=r"(r[0]), "=r"(r[1]) : "r"(addr));
}
__device__ __forceinline__ void ldsm_x2_trans(uint32_t* r, uint32_t addr) {
    asm volatile("ldmatrix.sync.aligned.m8n8.x2.trans.shared.b16 {%0,%1}, [%2];\n"
        : "=r"(r[0]), "=r"(r[1]) : "r"(addr));
}
__device__ __forceinline__ void mma_bf16(float* c, const uint32_t* a, const uint32_t* b) {
    asm volatile("mma.sync.aligned.m16n8k16.row.col.f32.bf16.bf16.f32 "
        "{%0,%1,%2,%3}, {%4,%5,%6,%7}, {%8,%9}, {%0,%1,%2,%3};\n"
        : "+f"(c[0]), "+f"(c[1]), "+f"(c[2]), "+f"(c[3])
        : "r"(a[0]), "r"(a[1]), "r"(a[2]), "r"(a[3]), "r"(b[0]), "r"(b[1]));
}
__device__ __forceinline__ void mma_f16(float* c, const uint32_t* a, const uint32_t* b) {
    asm volatile("mma.sync.aligned.m16n8k16.row.col.f32.f16.f16.f32 "
        "{%0,%1,%2,%3}, {%4,%5,%6,%7}, {%8,%9}, {%0,%1,%2,%3};\n"
        : "+f"(c[0]), "+f"(c[1]), "+f"(c[2]), "+f"(c[3])
        : "r"(a[0]), "r"(a[1]), "r"(a[2]), "r"(a[3]), "r"(b[0]), "r"(b[1]));
}
__device__ __forceinline__ void cp16(uint32_t dst, const void* src) {
    asm volatile("cp.async.cg.shared.global [%0], [%1], 16;\n" :: "r"(dst), "l"(src));
}
__device__ __forceinline__ void cp_commit() {
    asm volatile("cp.async.commit_group;\n" ::: "memory");
}
// bf16 hi/lo pack
__device__ __forceinline__ void pack_hilo(float a, float b, uint32_t& h, uint32_t& l) {
    __nv_bfloat16 ha = __float2bfloat16(a), hb = __float2bfloat16(b);
    __nv_bfloat162 H; H.x = ha; H.y = hb; h = *(uint32_t*)&H;
    __nv_bfloat162 L;
    L.x = __float2bfloat16(a - __bfloat162float(ha));
    L.y = __float2bfloat16(b - __bfloat162float(hb));
    l = *(uint32_t*)&L;
}
// fp16 hi/lo pack
__device__ __forceinline__ void pack_hilo_h(float a, float b, uint32_t& h, uint32_t& l) {
    __half ha = __float2half_rn(a), hb = __float2half_rn(b);
    __half2 H; H.x = ha; H.y = hb; h = *(uint32_t*)&H;
    __half2 L;
    L.x = __float2half_rn(a - __half2float(ha));
    L.y = __float2half_rn(b - __half2float(hb));
    l = *(uint32_t*)&L;
}

// ---------------- fp32 -> fp16 hi/lo split (activations) ----------------
__global__ void split2h_kernel(const float* __restrict__ in,
                               __half* __restrict__ hi,
                               __half* __restrict__ lo, int n4) {
    int i = blockIdx.x * blockDim.x + threadIdx.x;
    if (i >= n4) return;
    float4 v = ((const float4*)in)[i];
    uint2 hv, lv;
    pack_hilo_h(v.x, v.y, hv.x, lv.x);
    pack_hilo_h(v.z, v.w, hv.y, lv.y);
    *(uint2*)&hi[4 * i] = hv;
    *(uint2*)&lo[4 * i] = lv;
}

// ---------------- fp32 -> fp16 hi split (weights) ----------------
__global__ void split1h_kernel(const float* __restrict__ in,
                               __half* __restrict__ hi, int n4) {
    int i = blockIdx.x * blockDim.x + threadIdx.x;
    if (i >= n4) return;
    float4 v = ((const float4*)in)[i];
    __half2 H0, H1;
    H0.x = __float2half_rn(v.x); H0.y = __float2half_rn(v.y);
    H1.x = __float2half_rn(v.z); H1.y = __float2half_rn(v.w);
    uint2 hv; hv.x = *(uint32_t*)&H0; hv.y = *(uint32_t*)&H1;
    *(uint2*)&hi[4 * i] = hv;
}

// ---------------- fp16 2-MMA split GEMM, 3-stage cp.async (R8-proven mainloop) ----
// C[M,N] = A[M,K] * B[N,K]^T;  A = Ah+Al (fp16x2), B = Bh (fp16)
// split_out=1: write bf16 hi/lo to Ch/Cl.  split_out=0: write fp32 to C (+bias).
#define BM 128
#define BN 128
#define BK 32
#define SST 40         // smem row stride (half elems): 32 + 8 pad
#define NSTAGE 3
#define SM_A_HALFS (NSTAGE * 2 * BM * SST)
#define SM_B_HALFS (NSTAGE * BN * SST)
#define GM_SMEM_BYTES ((SM_A_HALFS + SM_B_HALFS) * 2)   // 92160

__global__ __launch_bounds__(256, 2)
void gemm_fp16x2(const __half* __restrict__ Ahi,
                 const __half* __restrict__ Alo,
                 const __half* __restrict__ Bh,
                 float* __restrict__ C,
                 __nv_bfloat16* __restrict__ Ch,
                 __nv_bfloat16* __restrict__ Cl,
                 const float* __restrict__ bias,
                 int Kdim, int Ndim, int split_out)
{
    extern __shared__ __half dsm[];
    __half* sA = dsm;                 // [(stage*2+part)*BM + row]*SST + col
    __half* sB = dsm + SM_A_HALFS;    // [stage*BN + row]*SST + col

    const int tid  = threadIdx.x;
    const int lane = tid & 31;
    const int warp = tid >> 5;
    const int warpM = warp >> 2;   // 0..1  -> 64 rows each
    const int warpN = warp & 3;    // 0..3  -> 32 cols each

    const int lr = tid >> 2;          // 0..63
    const int lc = (tid & 3) << 3;    // 0,8,16,24 half elems (16B)

    const size_t aBase = (size_t)blockIdx.y * BM * Kdim;
    const size_t bBase = (size_t)blockIdx.x * BN * Kdim;

    const int nk = Kdim / BK;   // 12

    float acc[4][4][4];
    #pragma unroll
    for (int mi = 0; mi < 4; mi++)
        #pragma unroll
        for (int ni = 0; ni < 4; ni++)
            #pragma unroll
            for (int q = 0; q < 4; q++) acc[mi][ni][q] = 0.f;

    auto load_tile = [&](int it) {
        const int st = it % NSTAGE;
        const int kt = it * BK;
        #pragma unroll
        for (int p = 0; p < 2; p++) {
            int r = lr + 64 * p;
            size_t goff = (size_t)r * Kdim + kt + lc;
            cp16(smem_u32(&sA[((st * 2 + 0) * BM + r) * SST + lc]), Ahi + aBase + goff);
            cp16(smem_u32(&sA[((st * 2 + 1) * BM + r) * SST + lc]), Alo + aBase + goff);
            cp16(smem_u32(&sB[(st * BN + r) * SST + lc]), Bh + bBase + goff);
        }
        cp_commit();
    };

    load_tile(0);
    load_tile(1);

    for (int it = 0; it < nk; it++) {
        if (it + 2 < nk) {
            load_tile(it + 2);
            asm volatile("cp.async.wait_group 2;\n" ::: "memory");
        } else if (it + 1 < nk) {
            asm volatile("cp.async.wait_group 1;\n" ::: "memory");
        } else {
            asm volatile("cp.async.wait_group 0;\n" ::: "memory");
        }
        __syncthreads();

        const int buf = it % NSTAGE;
        #pragma unroll
        for (int kk = 0; kk < 2; kk++) {
            uint32_t ah[4][4], al[4][4], bh[4][2];
            const int arow = warpM * 64 + (lane & 15);
            const int acol = kk * 16 + ((lane >> 4) << 3);
            #pragma unroll
            for (int mi = 0; mi < 4; mi++) {
                ldsm_x4(ah[mi], smem_u32(&sA[((buf * 2 + 0) * BM + arow + mi * 16) * SST + acol]));
                ldsm_x4(al[mi], smem_u32(&sA[((buf * 2 + 1) * BM + arow + mi * 16) * SST + acol]));
            }
            const int brow = warpN * 32 + (lane & 7);
            const int bcol = kk * 16 + ((lane >> 3) & 1) * 8;
            #pragma unroll
            for (int ni = 0; ni < 4; ni++) {
                ldsm_x2(bh[ni], smem_u32(&sB[(buf * BN + brow + ni * 8) * SST + bcol]));
            }
            #pragma unroll
            for (int mi = 0; mi < 4; mi++)
                #pragma unroll
                for (int ni = 0; ni < 4; ni++) {
                    mma_f16(acc[mi][ni], ah[mi], bh[ni]);  // Ah*Bh
                    mma_f16(acc[mi][ni], al[mi], bh[ni]);  // Al*Bh
                }
        }
        __syncthreads();
    }

    // epilogue
    if (split_out) {
        #pragma unroll
        for (int mi = 0; mi < 4; mi++) {
            int r = blockIdx.y * BM + warpM * 64 + mi * 16 + (lane >> 2);
            #pragma unroll
            for (int ni = 0; ni < 4; ni++) {
                int c = blockIdx.x * BN + warpN * 32 + ni * 8 + (lane & 3) * 2;
                uint32_t hv, lv;
                pack_hilo(acc[mi][ni][0], acc[mi][ni][1], hv, lv);
                *(uint32_t*)&Ch[(size_t)r * Ndim + c] = hv;
                *(uint32_t*)&Cl[(size_t)r * Ndim + c] = lv;
                pack_hilo(acc[mi][ni][2], acc[mi][ni][3], hv, lv);
                *(uint32_t*)&Ch[(size_t)(r + 8) * Ndim + c] = hv;
                *(uint32_t*)&Cl[(size_t)(r + 8) * Ndim + c] = lv;
            }
        }
    } else {
        #pragma unroll
        for (int mi = 0; mi < 4; mi++) {
            int r = blockIdx.y * BM + warpM * 64 + mi * 16 + (lane >> 2);
            #pragma unroll
            for (int ni = 0; ni < 4; ni++) {
                int c = blockIdx.x * BN + warpN * 32 + ni * 8 + (lane & 3) * 2;
                float bb0 = 0.f, bb1 = 0.f;
                if (bias) { bb0 = bias[c]; bb1 = bias[c + 1]; }
                float2 v0; v0.x = acc[mi][ni][0] + bb0; v0.y = acc[mi][ni][1] + bb1;
                float2 v1; v1.x = acc[mi][ni][2] + bb0; v1.y = acc[mi][ni][3] + bb1;
                *(float2*)&C[(size_t)r * Ndim + c]       = v0;
                *(float2*)&C[(size_t)(r + 8) * Ndim + c] = v1;
            }
        }
    }
}

// ---------------- tensor-core causal attention per (b,h), bf16x3 split ----------------
// smem (bf16, row stride AS=72): Qh,Ql [t][d]; Kh,Kl [s][d]; Vh,Vl [s][d]
// V fragments via ldmatrix.trans (no transpose staging needed).
// O staging (fp32 [64][68]) overlays Kh/Kl after S is computed.
#define AS 72
#define ATTN_SMEM (6 * 64 * AS * 2)   // 55296 bytes

__global__ __launch_bounds__(128)
void attn_tc_kernel(const __nv_bfloat16* __restrict__ qkvh,
                    const __nv_bfloat16* __restrict__ qkvl,
                    __half* __restrict__ Ohi,
                    __half* __restrict__ Olo)
{
    extern __shared__ __nv_bfloat16 sb[];
    __nv_bfloat16* sQh = sb;
    __nv_bfloat16* sQl = sb + 64 * AS;
    __nv_bfloat16* sKh = sb + 2 * 64 * AS;
    __nv_bfloat16* sKl = sb + 3 * 64 * AS;
    __nv_bfloat16* sVh = sb + 4 * 64 * AS;   // [s][d]
    __nv_bfloat16* sVl = sb + 5 * 64 * AS;
    float* sO = (float*)(sb + 2 * 64 * AS);  // overlays Kh/Kl (17408B <= 18432B)

    const int bh = blockIdx.x;
    const int b = bh / NHN, h = bh % NHN;
    const int tid = threadIdx.x;
    const int lane = tid & 31;
    const int warp = tid >> 5;
    const size_t base = (size_t)b * NT * F3;
    const int offq = h * NHS, offk = NC + h * NHS, offv = 2 * NC + h * NHS;

    // ---- async copy hi/lo qkv tiles into smem (no conversion, no transpose) ----
    for (int i = tid; i < 64 * 8; i += 128) {
        int t = i >> 3, j8 = (i & 7) * 8;            // row t, 8-elem (16B) chunk
        const size_t g = base + (size_t)t * F3 + j8;
        const uint32_t srow = t * AS + j8;
        cp16(smem_u32(&sQh[srow]), qkvh + g + offq);
        cp16(smem_u32(&sQl[srow]), qkvl + g + offq);
        cp16(smem_u32(&sKh[srow]), qkvh + g + offk);
        cp16(smem_u32(&sKl[srow]), qkvl + g + offk);
        cp16(smem_u32(&sVh[srow]), qkvh + g + offv);
        cp16(smem_u32(&sVl[srow]), qkvl + g + offv);
    }
    cp_commit();
    asm volatile("cp.async.wait_group 0;\n" ::: "memory");
    __syncthreads();

    // ---- S = Q @ K^T (per warp: rows m0..m0+15, all 64 cols) ----
    const int m0 = warp * 16;
    float accS[8][4];
    #pragma unroll
    for (int j = 0; j < 8; j++)
        #pragma unroll
        for (int q = 0; q < 4; q++) accS[j][q] = 0.f;

    #pragma unroll
    for (int ks = 0; ks < 4; ks++) {
        uint32_t qh[4], ql[4];
        const int arow = m0 + (lane & 15);
        const int acol = ks * 16 + ((lane >> 4) << 3);
        ldsm_x4(qh, smem_u32(&sQh[arow * AS + acol]));
        ldsm_x4(ql, smem_u32(&sQl[arow * AS + acol]));
        const int brow0 = lane & 7;
        const int bcol = ks * 16 + ((lane >> 3) & 1) * 8;
        #pragma unroll
        for (int j = 0; j < 8; j++) {
            uint32_t kh[2], kl[2];
            ldsm_x2(kh, smem_u32(&sKh[(j * 8 + brow0) * AS + bcol]));
            ldsm_x2(kl, smem_u32(&sKl[(j * 8 + brow0) * AS + bcol]));
            mma_bf16(accS[j], qh, kh);
            mma_bf16(accS[j], qh, kl);
            mma_bf16(accS[j], ql, kh);
        }
    }

    // ---- causal softmax in registers ----
    const int r0 = m0 + (lane >> 2);
    const int r8 = r0 + 8;
    const float scale = 0.125f;
    float mx0 = -1e30f, mx1 = -1e30f;
    #pragma unroll
    for (int j = 0; j < 8; j++) {
        int c = j * 8 + (lane & 3) * 2;
        accS[j][0] = (c     <= r0) ? accS[j][0] * scale : -1e30f;
        accS[j][1] = (c + 1 <= r0) ? accS[j][1] * scale : -1e30f;
        accS[j][2] = (c     <= r8) ? accS[j][2] * scale : -1e30f;
        accS[j][3] = (c + 1 <= r8) ? accS[j][3] * scale : -1e30f;
        mx0 = fmaxf(mx0, fmaxf(accS[j][0], accS[j][1]));
        mx1 = fmaxf(mx1, fmaxf(accS[j][2], accS[j][3]));
    }
    mx0 = fmaxf(mx0, __shfl_xor_sync(0xFFFFFFFF, mx0, 1));
    mx0 = fmaxf(mx0, __shfl_xor_sync(0xFFFFFFFF, mx0, 2));
    mx1 = fmaxf(mx1, __shfl_xor_sync(0xFFFFFFFF, mx1, 1));
    mx1 = fmaxf(mx1, __shfl_xor_sync(0xFFFFFFFF, mx1, 2));
    float sum0 = 0.f, sum1 = 0.f;
    #pragma unroll
    for (int j = 0; j < 8; j++) {
        accS[j][0] = __expf(accS[j][0] - mx0);
        accS[j][1] = __expf(accS[j][1] - mx0);
        accS[j][2] = __expf(accS[j][2] - mx1);
        accS[j][3] = __expf(accS[j][3] - mx1);
        sum0 += accS[j][0] + accS[j][1];
        sum1 += accS[j][2] + accS[j][3];
    }
    sum0 += __shfl_xor_sync(0xFFFFFFFF, sum0, 1);
    sum0 += __shfl_xor_sync(0xFFFFFFFF, sum0, 2);
    sum1 += __shfl_xor_sync(0xFFFFFFFF, sum1, 1);
    sum1 += __shfl_xor_sync(0xFFFFFFFF, sum1, 2);
    const float inv0 = 1.f / sum0, inv1 = 1.f / sum1;
    #pragma unroll
    for (int j = 0; j < 8; j++) {
        accS[j][0] *= inv0; accS[j][1] *= inv0;
        accS[j][2] *= inv1; accS[j][3] *= inv1;
    }

    // ---- O = P @ V  (P C-frag -> A-frag repack; V via ldmatrix.trans) ----
    float accO[8][4];
    #pragma unroll
    for (int j = 0; j < 8; j++)
        #pragma unroll
        for (int q = 0; q < 4; q++) accO[j][q] = 0.f;

    #pragma unroll
    for (int ks = 0; ks < 4; ks++) {
        const int j0 = 2 * ks, j1 = 2 * ks + 1;
        uint32_t ph[4], pl[4];
        pack_hilo(accS[j0][0], accS[j0][1], ph[0], pl[0]);
        pack_hilo(accS[j0][2], accS[j0][3], ph[1], pl[1]);
        pack_hilo(accS[j1][0], accS[j1][1], ph[2], pl[2]);
        pack_hilo(accS[j1][2], accS[j1][3], ph[3], pl[3]);
        // V trans-load: lanes 0-7 -> rows s0..s0+7, lanes 8-15 -> s0+8..s0+15
        const int trow = ks * 16 + ((lane >> 3) & 1) * 8 + (lane & 7);
        #pragma unroll
        for (int n = 0; n < 8; n++) {
            uint32_t vh[2], vl[2];
            ldsm_x2_trans(vh, smem_u32(&sVh[trow * AS + n * 8]));
            ldsm_x2_trans(vl, smem_u32(&sVl[trow * AS + n * 8]));
            mma_bf16(accO[n], ph, vh);
            mma_bf16(accO[n], ph, vl);
            mma_bf16(accO[n], pl, vh);
        }
    }

    // ---- stage O in smem (overlay on K), then coalesced fp16 hi/lo write ----
    __syncthreads();   // everyone done with sK reads
    #pragma unroll
    for (int j = 0; j < 8; j++) {
        int c = j * 8 + (lane & 3) * 2;
        sO[r0 * 68 + c]     = accO[j][0];
        sO[r0 * 68 + c + 1] = accO[j][1];
        sO[r8 * 68 + c]     = accO[j][2];
        sO[r8 * 68 + c + 1] = accO[j][3];
    }
    __syncthreads();

    for (int i = tid; i < 64 * 16; i += 128) {
        int t = i >> 4, j = i & 15;
        float4 a = *(float4*)&sO[t * 68 + 4 * j];
        uint2 hv, lv;
        pack_hilo_h(a.x, a.y, hv.x, lv.x);
        pack_hilo_h(a.z, a.w, hv.y, lv.y);
        size_t off = (size_t)(b * NT + t) * NC + h * NHS + 4 * j;
        *(uint2*)&Ohi[off] = hv;
        *(uint2*)&Olo[off] = lv;
    }
}

// ---------------- launch ----------------
extern "C" void kernel_launch(void* const* d_in, const int* in_sizes, int n_in,
                              void* d_out, int out_size) {
    const float* x    = (const float*)d_in[0];
    const float* Wqkv = (const float*)d_in[1];
    const float* Wp   = (const float*)d_in[2];
    const float* bp   = (const float*)d_in[3];
    float* out = (float*)d_out;

    void *pXhi, *pXlo, *pWqh, *pWph, *pQh, *pQl, *pAhi, *pAlo;
    cudaGetSymbolAddress(&pXhi, g_Xhi);
    cudaGetSymbolAddress(&pXlo, g_Xlo);
    cudaGetSymbolAddress(&pWqh, g_Wqh);
    cudaGetSymbolAddress(&pWph, g_Wph);
    cudaGetSymbolAddress(&pQh,  g_qkvh);
    cudaGetSymbolAddress(&pQl,  g_qkvl);
    cudaGetSymbolAddress(&pAhi, g_Ahi);
    cudaGetSymbolAddress(&pAlo, g_Alo);

    int n4;
    n4 = MTOK * NC / 4;
    split2h_kernel<<<(n4 + 255) / 256, 256>>>(x, (__half*)pXhi, (__half*)pXlo, n4);
    n4 = F3 * NC / 4;
    split1h_kernel<<<(n4 + 255) / 256, 256>>>(Wqkv, (__half*)pWqh, n4);
    n4 = NC * NC / 4;
    split1h_kernel<<<(n4 + 255) / 256, 256>>>(Wp, (__half*)pWph, n4);

    cudaFuncSetAttribute(gemm_fp16x2, cudaFuncAttributeMaxDynamicSharedMemorySize, GM_SMEM_BYTES);

    // qkv(hi/lo bf16) = X @ Wqkv^T : M=131072, N=1152, K=384
    gemm_fp16x2<<<dim3(F3 / BN, MTOK / BM), 256, GM_SMEM_BYTES>>>(
        (const __half*)pXhi, (const __half*)pXlo,
        (const __half*)pWqh,
        nullptr, (__nv_bfloat16*)pQh, (__nv_bfloat16*)pQl,
        nullptr, NC, F3, 1);

    cudaFuncSetAttribute(attn_tc_kernel, cudaFuncAttributeMaxDynamicSharedMemorySize, ATTN_SMEM);
    attn_tc_kernel<<<NB * NHN, 128, ATTN_SMEM>>>(
        (const __nv_bfloat16*)pQh, (const __nv_bfloat16*)pQl,
        (__half*)pAhi, (__half*)pAlo);

    // out = Attn @ Wp^T + bp : M=131072, N=384, K=384
    gemm_fp16x2<<<dim3(NC / BN, MTOK / BM), 256, GM_SMEM_BYTES>>>(
        (const __half*)pAhi, (const __half*)pAlo,
        (const __half*)pWph,
        out, nullptr, nullptr,
        bp, NC, NC, 0);
}

// round 15
// speedup vs baseline: 1.2442x; 1.1207x over previous
#include <cuda_runtime.h>
#include <cuda_bf16.h>
#include <cuda_fp16.h>
#include <stdint.h>

// Problem dims
#define NB   2048
#define NT   64
#define NC   384
#define NHN  6
#define NHS  64
#define MTOK (NB*NT)      // 131072 tokens
#define F3   (3*NC)       // 1152

// ---------------- workspaces (static device memory: allowed) ----------------
__device__ __half g_Xhi[MTOK * NC];
__device__ __half g_Xlo[MTOK * NC];
__device__ __half g_Wqh[F3 * NC];            // weights: fp16 hi only
__device__ __half g_Wph[NC * NC];
__device__ __nv_bfloat16 g_qkvh[MTOK * F3];  // qkv bf16 hi (302MB)
__device__ __nv_bfloat16 g_qkvl[MTOK * F3];  // qkv bf16 lo (302MB)
__device__ __half g_Ahi[MTOK * NC];          // attention output hi (fp16)
__device__ __half g_Alo[MTOK * NC];          // attention output lo (fp16)

// ---------------- helpers ----------------
__device__ __forceinline__ uint32_t smem_u32(const void* p) {
    return (uint32_t)__cvta_generic_to_shared(p);
}
__device__ __forceinline__ void ldsm_x4(uint32_t* r, uint32_t addr) {
    asm volatile("ldmatrix.sync.aligned.m8n8.x4.shared.b16 {%0,%1,%2,%3}, [%4];\n"
        : "=r"(r[0]), "=r"(r[1]), "=r"(r[2]), "=r"(r[3]) : "r"(addr));
}
__device__ __forceinline__ void ldsm_x2(uint32_t* r, uint32_t addr) {
    asm volatile("ldmatrix.sync.aligned.m8n8.x2.shared.b16 {%0,%1}, [%2];\n"
        : "=r"(r[0]), "=r"(r[1]) : "r"(addr));
}
__device__ __forceinline__ void ldsm_x2_trans(uint32_t* r, uint32_t addr) {
    asm volatile("ldmatrix.sync.aligned.m8n8.x2.trans.shared.b16 {%0,%1}, [%2];\n"
        : "=r"(r[0]), "=r"(r[1]) : "r"(addr));
}
__device__ __forceinline__ void mma_bf16(float* c, const uint32_t* a, const uint32_t* b) {
    asm volatile("mma.sync.aligned.m16n8k16.row.col.f32.bf16.bf16.f32 "
        "{%0,%1,%2,%3}, {%4,%5,%6,%7}, {%8,%9}, {%0,%1,%2,%3};\n"
        : "+f"(c[0]), "+f"(c[1]), "+f"(c[2]), "+f"(c[3])
        : "r"(a[0]), "r"(a[1]), "r"(a[2]), "r"(a[3]), "r"(b[0]), "r"(b[1]));
}
__device__ __forceinline__ void mma_f16(float* c, const uint32_t* a, const uint32_t* b) {
    asm volatile("mma.sync.aligned.m16n8k16.row.col.f32.f16.f16.f32 "
        "{%0,%1,%2,%3}, {%4,%5,%6,%7}, {%8,%9}, {%0,%1,%2,%3};\n"
        : "+f"(c[0]), "+f"(c[1]), "+f"(c[2]), "+f"(c[3])
        : "r"(a[0]), "r"(a[1]), "r"(a[2]), "r"(a[3]), "r"(b[0]), "r"(b[1]));
}
__device__ __forceinline__ void cp16(uint32_t dst, const void* src) {
    asm volatile("cp.async.cg.shared.global [%0], [%1], 16;\n" :: "r"(dst), "l"(src));
}
__device__ __forceinline__ void cp_commit() {
    asm volatile("cp.async.commit_group;\n" ::: "memory");
}
// bf16 hi/lo pack
__device__ __forceinline__ void pack_hilo(float a, float b, uint32_t& h, uint32_t& l) {
    __nv_bfloat16 ha = __float2bfloat16(a), hb = __float2bfloat16(b);
    __nv_bfloat162 H; H.x = ha; H.y = hb; h = *(uint32_t*)&H;
    __nv_bfloat162 L;
    L.x = __float2bfloat16(a - __bfloat162float(ha));
    L.y = __float2bfloat16(b - __bfloat162float(hb));
    l = *(uint32_t*)&L;
}
// fp16 hi/lo pack
__device__ __forceinline__ void pack_hilo_h(float a, float b, uint32_t& h, uint32_t& l) {
    __half ha = __float2half_rn(a), hb = __float2half_rn(b);
    __half2 H; H.x = ha; H.y = hb; h = *(uint32_t*)&H;
    __half2 L;
    L.x = __float2half_rn(a - __half2float(ha));
    L.y = __float2half_rn(b - __half2float(hb));
    l = *(uint32_t*)&L;
}

// ---------------- fp32 -> fp16 hi/lo split (activations) ----------------
__global__ void split2h_kernel(const float* __restrict__ in,
                               __half* __restrict__ hi,
                               __half* __restrict__ lo, int n4) {
    int i = blockIdx.x * blockDim.x + threadIdx.x;
    if (i >= n4) return;
    float4 v = ((const float4*)in)[i];
    uint2 hv, lv;
    pack_hilo_h(v.x, v.y, hv.x, lv.x);
    pack_hilo_h(v.z, v.w, hv.y, lv.y);
    *(uint2*)&hi[4 * i] = hv;
    *(uint2*)&lo[4 * i] = lv;
}

// ---------------- fp32 -> fp16 hi split (weights) ----------------
__global__ void split1h_kernel(const float* __restrict__ in,
                               __half* __restrict__ hi, int n4) {
    int i = blockIdx.x * blockDim.x + threadIdx.x;
    if (i >= n4) return;
    float4 v = ((const float4*)in)[i];
    __half2 H0, H1;
    H0.x = __float2half_rn(v.x); H0.y = __float2half_rn(v.y);
    H1.x = __float2half_rn(v.z); H1.y = __float2half_rn(v.w);
    uint2 hv; hv.x = *(uint32_t*)&H0; hv.y = *(uint32_t*)&H1;
    *(uint2*)&hi[4 * i] = hv;
}

// ---------------- fp16 2-MMA split GEMM, BK=64, 2-stage cp.async ----------------
// C[M,N] = A[M,K] * B[N,K]^T;  A = Ah+Al (fp16x2), B = Bh (fp16)
// split_out=1: write bf16 hi/lo to Ch/Cl.  split_out=0: write fp32 to C (+bias).
#define BM 128
#define BN 128
#define BK 64
#define SST 72         // smem row stride (half elems): 64 + 8 pad
#define NSTAGE 2
#define SM_A_HALFS (NSTAGE * 2 * BM * SST)   // 36864
#define SM_B_HALFS (NSTAGE * BN * SST)       // 18432
#define GM_SMEM_BYTES ((SM_A_HALFS + SM_B_HALFS) * 2)   // 110592

__global__ __launch_bounds__(256, 2)
void gemm_fp16x2(const __half* __restrict__ Ahi,
                 const __half* __restrict__ Alo,
                 const __half* __restrict__ Bh,
                 float* __restrict__ C,
                 __nv_bfloat16* __restrict__ Ch,
                 __nv_bfloat16* __restrict__ Cl,
                 const float* __restrict__ bias,
                 int Kdim, int Ndim, int split_out)
{
    extern __shared__ __half dsm[];
    __half* sA = dsm;                 // [(stage*2+part)*BM + row]*SST + col
    __half* sB = dsm + SM_A_HALFS;    // [stage*BN + row]*SST + col

    const int tid  = threadIdx.x;
    const int lane = tid & 31;
    const int warp = tid >> 5;
    const int warpM = warp >> 2;   // 0..1  -> 64 rows each
    const int warpN = warp & 3;    // 0..3  -> 32 cols each

    const size_t aBase = (size_t)blockIdx.y * BM * Kdim;
    const size_t bBase = (size_t)blockIdx.x * BN * Kdim;

    const int nk = Kdim / BK;   // 6

    float acc[4][4][4];
    #pragma unroll
    for (int mi = 0; mi < 4; mi++)
        #pragma unroll
        for (int ni = 0; ni < 4; ni++)
            #pragma unroll
            for (int q = 0; q < 4; q++) acc[mi][ni][q] = 0.f;

    auto load_tile = [&](int it) {
        const int st = it & 1;
        const int kt = it * BK;
        #pragma unroll
        for (int i = 0; i < 4; i++) {
            int idx = tid + i * 256;       // 0..1023
            int r = idx >> 3;              // 0..127
            int c8 = (idx & 7) * 8;        // 0..56 (16B chunks)
            size_t goff = (size_t)r * Kdim + kt + c8;
            cp16(smem_u32(&sA[((st * 2 + 0) * BM + r) * SST + c8]), Ahi + aBase + goff);
            cp16(smem_u32(&sA[((st * 2 + 1) * BM + r) * SST + c8]), Alo + aBase + goff);
            cp16(smem_u32(&sB[(st * BN + r) * SST + c8]), Bh + bBase + goff);
        }
        cp_commit();
    };

    load_tile(0);

    for (int it = 0; it < nk; it++) {
        if (it + 1 < nk) {
            load_tile(it + 1);
            asm volatile("cp.async.wait_group 1;\n" ::: "memory");
        } else {
            asm volatile("cp.async.wait_group 0;\n" ::: "memory");
        }
        __syncthreads();

        const int buf = it & 1;
        #pragma unroll
        for (int kk = 0; kk < 4; kk++) {
            uint32_t ah[4][4], al[4][4], bh[4][2];
            const int arow = warpM * 64 + (lane & 15);
            const int acol = kk * 16 + ((lane >> 4) << 3);
            #pragma unroll
            for (int mi = 0; mi < 4; mi++) {
                ldsm_x4(ah[mi], smem_u32(&sA[((buf * 2 + 0) * BM + arow + mi * 16) * SST + acol]));
                ldsm_x4(al[mi], smem_u32(&sA[((buf * 2 + 1) * BM + arow + mi * 16) * SST + acol]));
            }
            const int brow = warpN * 32 + (lane & 7);
            const int bcol = kk * 16 + ((lane >> 3) & 1) * 8;
            #pragma unroll
            for (int ni = 0; ni < 4; ni++) {
                ldsm_x2(bh[ni], smem_u32(&sB[(buf * BN + brow + ni * 8) * SST + bcol]));
            }
            #pragma unroll
            for (int mi = 0; mi < 4; mi++)
                #pragma unroll
                for (int ni = 0; ni < 4; ni++) {
                    mma_f16(acc[mi][ni], ah[mi], bh[ni]);  // Ah*Bh
                    mma_f16(acc[mi][ni], al[mi], bh[ni]);  // Al*Bh
                }
        }
        __syncthreads();
    }

    // epilogue
    if (split_out) {
        #pragma unroll
        for (int mi = 0; mi < 4; mi++) {
            int r = blockIdx.y * BM + warpM * 64 + mi * 16 + (lane >> 2);
            #pragma unroll
            for (int ni = 0; ni < 4; ni++) {
                int c = blockIdx.x * BN + warpN * 32 + ni * 8 + (lane & 3) * 2;
                uint32_t hv, lv;
                pack_hilo(acc[mi][ni][0], acc[mi][ni][1], hv, lv);
                *(uint32_t*)&Ch[(size_t)r * Ndim + c] = hv;
                *(uint32_t*)&Cl[(size_t)r * Ndim + c] = lv;
                pack_hilo(acc[mi][ni][2], acc[mi][ni][3], hv, lv);
                *(uint32_t*)&Ch[(size_t)(r + 8) * Ndim + c] = hv;
                *(uint32_t*)&Cl[(size_t)(r + 8) * Ndim + c] = lv;
            }
        }
    } else {
        #pragma unroll
        for (int mi = 0; mi < 4; mi++) {
            int r = blockIdx.y * BM + warpM * 64 + mi * 16 + (lane >> 2);
            #pragma unroll
            for (int ni = 0; ni < 4; ni++) {
                int c = blockIdx.x * BN + warpN * 32 + ni * 8 + (lane & 3) * 2;
                float bb0 = 0.f, bb1 = 0.f;
                if (bias) { bb0 = bias[c]; bb1 = bias[c + 1]; }
                float2 v0; v0.x = acc[mi][ni][0] + bb0; v0.y = acc[mi][ni][1] + bb1;
                float2 v1; v1.x = acc[mi][ni][2] + bb0; v1.y = acc[mi][ni][3] + bb1;
                *(float2*)&C[(size_t)r * Ndim + c]       = v0;
                *(float2*)&C[(size_t)(r + 8) * Ndim + c] = v1;
            }
        }
    }
}

// ---------------- tensor-core causal attention per (b,h), bf16x3 split ----------------
// smem (bf16, row stride AS=72): Qh,Ql [t][d]; Kh,Kl [s][d]; Vh,Vl [s][d]
// V fragments via ldmatrix.trans (no transpose staging needed).
// O staging (fp32 [64][68]) overlays Kh/Kl after S is computed.
#define AS 72
#define ATTN_SMEM (6 * 64 * AS * 2)   // 55296 bytes

__global__ __launch_bounds__(128)
void attn_tc_kernel(const __nv_bfloat16* __restrict__ qkvh,
                    const __nv_bfloat16* __restrict__ qkvl,
                    __half* __restrict__ Ohi,
                    __half* __restrict__ Olo)
{
    extern __shared__ __nv_bfloat16 sb[];
    __nv_bfloat16* sQh = sb;
    __nv_bfloat16* sQl = sb + 64 * AS;
    __nv_bfloat16* sKh = sb + 2 * 64 * AS;
    __nv_bfloat16* sKl = sb + 3 * 64 * AS;
    __nv_bfloat16* sVh = sb + 4 * 64 * AS;   // [s][d]
    __nv_bfloat16* sVl = sb + 5 * 64 * AS;
    float* sO = (float*)(sb + 2 * 64 * AS);  // overlays Kh/Kl (17408B <= 18432B)

    const int bh = blockIdx.x;
    const int b = bh / NHN, h = bh % NHN;
    const int tid = threadIdx.x;
    const int lane = tid & 31;
    const int warp = tid >> 5;
    const size_t base = (size_t)b * NT * F3;
    const int offq = h * NHS, offk = NC + h * NHS, offv = 2 * NC + h * NHS;

    // ---- async copy hi/lo qkv tiles into smem (no conversion, no transpose) ----
    for (int i = tid; i < 64 * 8; i += 128) {
        int t = i >> 3, j8 = (i & 7) * 8;            // row t, 8-elem (16B) chunk
        const size_t g = base + (size_t)t * F3 + j8;
        const uint32_t srow = t * AS + j8;
        cp16(smem_u32(&sQh[srow]), qkvh + g + offq);
        cp16(smem_u32(&sQl[srow]), qkvl + g + offq);
        cp16(smem_u32(&sKh[srow]), qkvh + g + offk);
        cp16(smem_u32(&sKl[srow]), qkvl + g + offk);
        cp16(smem_u32(&sVh[srow]), qkvh + g + offv);
        cp16(smem_u32(&sVl[srow]), qkvl + g + offv);
    }
    cp_commit();
    asm volatile("cp.async.wait_group 0;\n" ::: "memory");
    __syncthreads();

    // ---- S = Q @ K^T (per warp: rows m0..m0+15, all 64 cols) ----
    const int m0 = warp * 16;
    float accS[8][4];
    #pragma unroll
    for (int j = 0; j < 8; j++)
        #pragma unroll
        for (int q = 0; q < 4; q++) accS[j][q] = 0.f;

    #pragma unroll
    for (int ks = 0; ks < 4; ks++) {
        uint32_t qh[4], ql[4];
        const int arow = m0 + (lane & 15);
        const int acol = ks * 16 + ((lane >> 4) << 3);
        ldsm_x4(qh, smem_u32(&sQh[arow * AS + acol]));
        ldsm_x4(ql, smem_u32(&sQl[arow * AS + acol]));
        const int brow0 = lane & 7;
        const int bcol = ks * 16 + ((lane >> 3) & 1) * 8;
        #pragma unroll
        for (int j = 0; j < 8; j++) {
            uint32_t kh[2], kl[2];
            ldsm_x2(kh, smem_u32(&sKh[(j * 8 + brow0) * AS + bcol]));
            ldsm_x2(kl, smem_u32(&sKl[(j * 8 + brow0) * AS + bcol]));
            mma_bf16(accS[j], qh, kh);
            mma_bf16(accS[j], qh, kl);
            mma_bf16(accS[j], ql, kh);
        }
    }

    // ---- causal softmax in registers ----
    const int r0 = m0 + (lane >> 2);
    const int r8 = r0 + 8;
    const float scale = 0.125f;
    float mx0 = -1e30f, mx1 = -1e30f;
    #pragma unroll
    for (int j = 0; j < 8; j++) {
        int c = j * 8 + (lane & 3) * 2;
        accS[j][0] = (c     <= r0) ? accS[j][0] * scale : -1e30f;
        accS[j][1] = (c + 1 <= r0) ? accS[j][1] * scale : -1e30f;
        accS[j][2] = (c     <= r8) ? accS[j][2] * scale : -1e30f;
        accS[j][3] = (c + 1 <= r8) ? accS[j][3] * scale : -1e30f;
        mx0 = fmaxf(mx0, fmaxf(accS[j][0], accS[j][1]));
        mx1 = fmaxf(mx1, fmaxf(accS[j][2], accS[j][3]));
    }
    mx0 = fmaxf(mx0, __shfl_xor_sync(0xFFFFFFFF, mx0, 1));
    mx0 = fmaxf(mx0, __shfl_xor_sync(0xFFFFFFFF, mx0, 2));
    mx1 = fmaxf(mx1, __shfl_xor_sync(0xFFFFFFFF, mx1, 1));
    mx1 = fmaxf(mx1, __shfl_xor_sync(0xFFFFFFFF, mx1, 2));
    float sum0 = 0.f, sum1 = 0.f;
    #pragma unroll
    for (int j = 0; j < 8; j++) {
        accS[j][0] = __expf(accS[j][0] - mx0);
        accS[j][1] = __expf(accS[j][1] - mx0);
        accS[j][2] = __expf(accS[j][2] - mx1);
        accS[j][3] = __expf(accS[j][3] - mx1);
        sum0 += accS[j][0] + accS[j][1];
        sum1 += accS[j][2] + accS[j][3];
    }
    sum0 += __shfl_xor_sync(0xFFFFFFFF, sum0, 1);
    sum0 += __shfl_xor_sync(0xFFFFFFFF, sum0, 2);
    sum1 += __shfl_xor_sync(0xFFFFFFFF, sum1, 1);
    sum1 += __shfl_xor_sync(0xFFFFFFFF, sum1, 2);
    const float inv0 = 1.f / sum0, inv1 = 1.f / sum1;
    #pragma unroll
    for (int j = 0; j < 8; j++) {
        accS[j][0] *= inv0; accS[j][1] *= inv0;
        accS[j][2] *= inv1; accS[j][3] *= inv1;
    }

    // ---- O = P @ V  (P C-frag -> A-frag repack; V via ldmatrix.trans) ----
    float accO[8][4];
    #pragma unroll
    for (int j = 0; j < 8; j++)
        #pragma unroll
        for (int q = 0; q < 4; q++) accO[j][q] = 0.f;

    #pragma unroll
    for (int ks = 0; ks < 4; ks++) {
        const int j0 = 2 * ks, j1 = 2 * ks + 1;
        uint32_t ph[4], pl[4];
        pack_hilo(accS[j0][0], accS[j0][1], ph[0], pl[0]);
        pack_hilo(accS[j0][2], accS[j0][3], ph[1], pl[1]);
        pack_hilo(accS[j1][0], accS[j1][1], ph[2], pl[2]);
        pack_hilo(accS[j1][2], accS[j1][3], ph[3], pl[3]);
        // V trans-load: lanes 0-7 -> rows s0..s0+7, lanes 8-15 -> s0+8..s0+15
        const int trow = ks * 16 + ((lane >> 3) & 1) * 8 + (lane & 7);
        #pragma unroll
        for (int n = 0; n < 8; n++) {
            uint32_t vh[2], vl[2];
            ldsm_x2_trans(vh, smem_u32(&sVh[trow * AS + n * 8]));
            ldsm_x2_trans(vl, smem_u32(&sVl[trow * AS + n * 8]));
            mma_bf16(accO[n], ph, vh);
            mma_bf16(accO[n], ph, vl);
            mma_bf16(accO[n], pl, vh);
        }
    }

    // ---- stage O in smem (overlay on K), then coalesced fp16 hi/lo write ----
    __syncthreads();   // everyone done with sK reads
    #pragma unroll
    for (int j = 0; j < 8; j++) {
        int c = j * 8 + (lane & 3) * 2;
        sO[r0 * 68 + c]     = accO[j][0];
        sO[r0 * 68 + c + 1] = accO[j][1];
        sO[r8 * 68 + c]     = accO[j][2];
        sO[r8 * 68 + c + 1] = accO[j][3];
    }
    __syncthreads();

    for (int i = tid; i < 64 * 16; i += 128) {
        int t = i >> 4, j = i & 15;
        float4 a = *(float4*)&sO[t * 68 + 4 * j];
        uint2 hv, lv;
        pack_hilo_h(a.x, a.y, hv.x, lv.x);
        pack_hilo_h(a.z, a.w, hv.y, lv.y);
        size_t off = (size_t)(b * NT + t) * NC + h * NHS + 4 * j;
        *(uint2*)&Ohi[off] = hv;
        *(uint2*)&Olo[off] = lv;
    }
}

// ---------------- launch ----------------
extern "C" void kernel_launch(void* const* d_in, const int* in_sizes, int n_in,
                              void* d_out, int out_size) {
    const float* x    = (const float*)d_in[0];
    const float* Wqkv = (const float*)d_in[1];
    const float* Wp   = (const float*)d_in[2];
    const float* bp   = (const float*)d_in[3];
    float* out = (float*)d_out;

    void *pXhi, *pXlo, *pWqh, *pWph, *pQh, *pQl, *pAhi, *pAlo;
    cudaGetSymbolAddress(&pXhi, g_Xhi);
    cudaGetSymbolAddress(&pXlo, g_Xlo);
    cudaGetSymbolAddress(&pWqh, g_Wqh);
    cudaGetSymbolAddress(&pWph, g_Wph);
    cudaGetSymbolAddress(&pQh,  g_qkvh);
    cudaGetSymbolAddress(&pQl,  g_qkvl);
    cudaGetSymbolAddress(&pAhi, g_Ahi);
    cudaGetSymbolAddress(&pAlo, g_Alo);

    int n4;
    n4 = MTOK * NC / 4;
    split2h_kernel<<<(n4 + 255) / 256, 256>>>(x, (__half*)pXhi, (__half*)pXlo, n4);
    n4 = F3 * NC / 4;
    split1h_kernel<<<(n4 + 255) / 256, 256>>>(Wqkv, (__half*)pWqh, n4);
    n4 = NC * NC / 4;
    split1h_kernel<<<(n4 + 255) / 256, 256>>>(Wp, (__half*)pWph, n4);

    cudaFuncSetAttribute(gemm_fp16x2, cudaFuncAttributeMaxDynamicSharedMemorySize, GM_SMEM_BYTES);

    // qkv(hi/lo bf16) = X @ Wqkv^T : M=131072, N=1152, K=384
    gemm_fp16x2<<<dim3(F3 / BN, MTOK / BM), 256, GM_SMEM_BYTES>>>(
        (const __half*)pXhi, (const __half*)pXlo,
        (const __half*)pWqh,
        nullptr, (__nv_bfloat16*)pQh, (__nv_bfloat16*)pQl,
        nullptr, NC, F3, 1);

    cudaFuncSetAttribute(attn_tc_kernel, cudaFuncAttributeMaxDynamicSharedMemorySize, ATTN_SMEM);
    attn_tc_kernel<<<NB * NHN, 128, ATTN_SMEM>>>(
        (const __nv_bfloat16*)pQh, (const __nv_bfloat16*)pQl,
        (__half*)pAhi, (__half*)pAlo);

    // out = Attn @ Wp^T + bp : M=131072, N=384, K=384
    gemm_fp16x2<<<dim3(NC / BN, MTOK / BM), 256, GM_SMEM_BYTES>>>(
        (const __half*)pAhi, (const __half*)pAlo,
        (const __half*)pWph,
        out, nullptr, nullptr,
        bp, NC, NC, 0);
}

// round 17
// speedup vs baseline: 1.6960x; 1.3632x over previous
#include <cuda_runtime.h>
#include <cuda_bf16.h>
#include <cuda_fp16.h>
#include <stdint.h>

// Problem dims
#define NB   2048
#define NT   64
#define NC   384
#define NHN  6
#define NHS  64
#define MTOK (NB*NT)      // 131072 tokens
#define F3   (3*NC)       // 1152

// ---------------- workspaces (static device memory: allowed) ----------------
__device__ __half g_Xh[MTOK * NC];           // x fp16 hi only
__device__ __half g_Wqh[F3 * NC];            // weights fp16 hi only
__device__ __half g_Wph[NC * NC];
__device__ __nv_bfloat16 g_qkvh[MTOK * F3];  // qkv bf16 hi (302MB)
__device__ __nv_bfloat16 g_qkvl[MTOK * F3];  // qkv bf16 lo (302MB)
__device__ __half g_Ah[MTOK * NC];           // attention output fp16 hi only

// ---------------- helpers ----------------
__device__ __forceinline__ uint32_t smem_u32(const void* p) {
    return (uint32_t)__cvta_generic_to_shared(p);
}
__device__ __forceinline__ void ldsm_x4(uint32_t* r, uint32_t addr) {
    asm volatile("ldmatrix.sync.aligned.m8n8.x4.shared.b16 {%0,%1,%2,%3}, [%4];\n"
        : "=r"(r[0]), "=r"(r[1]), "=r"(r[2]), "=r"(r[3]) : "r"(addr));
}
__device__ __forceinline__ void ldsm_x2(uint32_t* r, uint32_t addr) {
    asm volatile("ldmatrix.sync.aligned.m8n8.x2.shared.b16 {%0,%1}, [%2];\n"
        : "=r"(r[0]), "=r"(r[1]) : "r"(addr));
}
__device__ __forceinline__ void ldsm_x2_trans(uint32_t* r, uint32_t addr) {
    asm volatile("ldmatrix.sync.aligned.m8n8.x2.trans.shared.b16 {%0,%1}, [%2];\n"
        : "=r"(r[0]), "=r"(r[1]) : "r"(addr));
}
__device__ __forceinline__ void mma_bf16(float* c, const uint32_t* a, const uint32_t* b) {
    asm volatile("mma.sync.aligned.m16n8k16.row.col.f32.bf16.bf16.f32 "
        "{%0,%1,%2,%3}, {%4,%5,%6,%7}, {%8,%9}, {%0,%1,%2,%3};\n"
        : "+f"(c[0]), "+f"(c[1]), "+f"(c[2]), "+f"(c[3])
        : "r"(a[0]), "r"(a[1]), "r"(a[2]), "r"(a[3]), "r"(b[0]), "r"(b[1]));
}
__device__ __forceinline__ void mma_f16(float* c, const uint32_t* a, const uint32_t* b) {
    asm volatile("mma.sync.aligned.m16n8k16.row.col.f32.f16.f16.f32 "
        "{%0,%1,%2,%3}, {%4,%5,%6,%7}, {%8,%9}, {%0,%1,%2,%3};\n"
        : "+f"(c[0]), "+f"(c[1]), "+f"(c[2]), "+f"(c[3])
        : "r"(a[0]), "r"(a[1]), "r"(a[2]), "r"(a[3]), "r"(b[0]), "r"(b[1]));
}
__device__ __forceinline__ void cp16(uint32_t dst, const void* src) {
    asm volatile("cp.async.cg.shared.global [%0], [%1], 16;\n" :: "r"(dst), "l"(src));
}
__device__ __forceinline__ void cp_commit() {
    asm volatile("cp.async.commit_group;\n" ::: "memory");
}
// bf16 hi/lo pack
__device__ __forceinline__ void pack_hilo(float a, float b, uint32_t& h, uint32_t& l) {
    __nv_bfloat16 ha = __float2bfloat16(a), hb = __float2bfloat16(b);
    __nv_bfloat162 H; H.x = ha; H.y = hb; h = *(uint32_t*)&H;
    __nv_bfloat162 L;
    L.x = __float2bfloat16(a - __bfloat162float(ha));
    L.y = __float2bfloat16(b - __bfloat162float(hb));
    l = *(uint32_t*)&L;
}

// ---------------- fp32 -> fp16 (round-nearest) ----------------
__global__ void split1h_kernel(const float* __restrict__ in,
                               __half* __restrict__ hi, int n4) {
    int i = blockIdx.x * blockDim.x + threadIdx.x;
    if (i >= n4) return;
    float4 v = ((const float4*)in)[i];
    __half2 H0, H1;
    H0.x = __float2half_rn(v.x); H0.y = __float2half_rn(v.y);
    H1.x = __float2half_rn(v.z); H1.y = __float2half_rn(v.w);
    uint2 hv; hv.x = *(uint32_t*)&H0; hv.y = *(uint32_t*)&H1;
    *(uint2*)&hi[4 * i] = hv;
}

// ---------------- fp16 GEMM (1 MMA), BK=64, 2-stage cp.async ----------------
// C[M,N] = A[M,K] * B[N,K]^T;  A, B fp16, fp32 accum.
// split_out=1: write bf16 hi/lo to Ch/Cl.  split_out=0: write fp32 to C (+bias).
#define BM 128
#define BN 128
#define BK 64
#define SST 72         // smem row stride (half elems): 64 + 8 pad
#define NSTAGE 2
#define SM_A_HALFS (NSTAGE * BM * SST)       // 18432
#define SM_B_HALFS (NSTAGE * BN * SST)       // 18432
#define GM_SMEM_BYTES ((SM_A_HALFS + SM_B_HALFS) * 2)   // 73728

__global__ __launch_bounds__(256, 2)
void gemm_fp16(const __half* __restrict__ Ah,
               const __half* __restrict__ Bh,
               float* __restrict__ C,
               __nv_bfloat16* __restrict__ Ch,
               __nv_bfloat16* __restrict__ Cl,
               const float* __restrict__ bias,
               int Kdim, int Ndim, int split_out)
{
    extern __shared__ __half dsm[];
    __half* sA = dsm;                 // [stage*BM + row]*SST + col
    __half* sB = dsm + SM_A_HALFS;    // [stage*BN + row]*SST + col

    const int tid  = threadIdx.x;
    const int lane = tid & 31;
    const int warp = tid >> 5;
    const int warpM = warp >> 2;   // 0..1  -> 64 rows each
    const int warpN = warp & 3;    // 0..3  -> 32 cols each

    const size_t aBase = (size_t)blockIdx.y * BM * Kdim;
    const size_t bBase = (size_t)blockIdx.x * BN * Kdim;

    const int nk = Kdim / BK;   // 6

    float acc[4][4][4];
    #pragma unroll
    for (int mi = 0; mi < 4; mi++)
        #pragma unroll
        for (int ni = 0; ni < 4; ni++)
            #pragma unroll
            for (int q = 0; q < 4; q++) acc[mi][ni][q] = 0.f;

    auto load_tile = [&](int it) {
        const int st = it & 1;
        const int kt = it * BK;
        #pragma unroll
        for (int i = 0; i < 4; i++) {
            int idx = tid + i * 256;       // 0..1023
            int r = idx >> 3;              // 0..127
            int c8 = (idx & 7) * 8;        // 0..56 (16B chunks)
            size_t goff = (size_t)r * Kdim + kt + c8;
            cp16(smem_u32(&sA[(st * BM + r) * SST + c8]), Ah + aBase + goff);
            cp16(smem_u32(&sB[(st * BN + r) * SST + c8]), Bh + bBase + goff);
        }
        cp_commit();
    };

    load_tile(0);

    for (int it = 0; it < nk; it++) {
        if (it + 1 < nk) {
            load_tile(it + 1);
            asm volatile("cp.async.wait_group 1;\n" ::: "memory");
        } else {
            asm volatile("cp.async.wait_group 0;\n" ::: "memory");
        }
        __syncthreads();

        const int buf = it & 1;
        #pragma unroll
        for (int kk = 0; kk < 4; kk++) {
            uint32_t ah[4][4], bh[4][2];
            const int arow = warpM * 64 + (lane & 15);
            const int acol = kk * 16 + ((lane >> 4) << 3);
            #pragma unroll
            for (int mi = 0; mi < 4; mi++) {
                ldsm_x4(ah[mi], smem_u32(&sA[(buf * BM + arow + mi * 16) * SST + acol]));
            }
            const int brow = warpN * 32 + (lane & 7);
            const int bcol = kk * 16 + ((lane >> 3) & 1) * 8;
            #pragma unroll
            for (int ni = 0; ni < 4; ni++) {
                ldsm_x2(bh[ni], smem_u32(&sB[(buf * BN + brow + ni * 8) * SST + bcol]));
            }
            #pragma unroll
            for (int mi = 0; mi < 4; mi++)
                #pragma unroll
                for (int ni = 0; ni < 4; ni++) {
                    mma_f16(acc[mi][ni], ah[mi], bh[ni]);
                }
        }
        __syncthreads();
    }

    // epilogue
    if (split_out) {
        #pragma unroll
        for (int mi = 0; mi < 4; mi++) {
            int r = blockIdx.y * BM + warpM * 64 + mi * 16 + (lane >> 2);
            #pragma unroll
            for (int ni = 0; ni < 4; ni++) {
                int c = blockIdx.x * BN + warpN * 32 + ni * 8 + (lane & 3) * 2;
                uint32_t hv, lv;
                pack_hilo(acc[mi][ni][0], acc[mi][ni][1], hv, lv);
                *(uint32_t*)&Ch[(size_t)r * Ndim + c] = hv;
                *(uint32_t*)&Cl[(size_t)r * Ndim + c] = lv;
                pack_hilo(acc[mi][ni][2], acc[mi][ni][3], hv, lv);
                *(uint32_t*)&Ch[(size_t)(r + 8) * Ndim + c] = hv;
                *(uint32_t*)&Cl[(size_t)(r + 8) * Ndim + c] = lv;
            }
        }
    } else {
        #pragma unroll
        for (int mi = 0; mi < 4; mi++) {
            int r = blockIdx.y * BM + warpM * 64 + mi * 16 + (lane >> 2);
            #pragma unroll
            for (int ni = 0; ni < 4; ni++) {
                int c = blockIdx.x * BN + warpN * 32 + ni * 8 + (lane & 3) * 2;
                float bb0 = 0.f, bb1 = 0.f;
                if (bias) { bb0 = bias[c]; bb1 = bias[c + 1]; }
                float2 v0; v0.x = acc[mi][ni][0] + bb0; v0.y = acc[mi][ni][1] + bb1;
                float2 v1; v1.x = acc[mi][ni][2] + bb0; v1.y = acc[mi][ni][3] + bb1;
                *(float2*)&C[(size_t)r * Ndim + c]       = v0;
                *(float2*)&C[(size_t)(r + 8) * Ndim + c] = v1;
            }
        }
    }
}

// ---------------- tensor-core causal attention per (b,h), bf16x3 split ----------------
// smem (bf16, row stride AS=72): Qh,Ql [t][d]; Kh,Kl [s][d]; Vh,Vl [s][d]
// V fragments via ldmatrix.trans. O staging (fp32 [64][68]) overlays Kh/Kl.
#define AS 72
#define ATTN_SMEM (6 * 64 * AS * 2)   // 55296 bytes

__global__ __launch_bounds__(128)
void attn_tc_kernel(const __nv_bfloat16* __restrict__ qkvh,
                    const __nv_bfloat16* __restrict__ qkvl,
                    __half* __restrict__ Oh)
{
    extern __shared__ __nv_bfloat16 sb[];
    __nv_bfloat16* sQh = sb;
    __nv_bfloat16* sQl = sb + 64 * AS;
    __nv_bfloat16* sKh = sb + 2 * 64 * AS;
    __nv_bfloat16* sKl = sb + 3 * 64 * AS;
    __nv_bfloat16* sVh = sb + 4 * 64 * AS;   // [s][d]
    __nv_bfloat16* sVl = sb + 5 * 64 * AS;
    float* sO = (float*)(sb + 2 * 64 * AS);  // overlays Kh/Kl (17408B <= 18432B)

    const int bh = blockIdx.x;
    const int b = bh / NHN, h = bh % NHN;
    const int tid = threadIdx.x;
    const int lane = tid & 31;
    const int warp = tid >> 5;
    const size_t base = (size_t)b * NT * F3;
    const int offq = h * NHS, offk = NC + h * NHS, offv = 2 * NC + h * NHS;

    // ---- async copy hi/lo qkv tiles into smem ----
    for (int i = tid; i < 64 * 8; i += 128) {
        int t = i >> 3, j8 = (i & 7) * 8;            // row t, 8-elem (16B) chunk
        const size_t g = base + (size_t)t * F3 + j8;
        const uint32_t srow = t * AS + j8;
        cp16(smem_u32(&sQh[srow]), qkvh + g + offq);
        cp16(smem_u32(&sQl[srow]), qkvl + g + offq);
        cp16(smem_u32(&sKh[srow]), qkvh + g + offk);
        cp16(smem_u32(&sKl[srow]), qkvl + g + offk);
        cp16(smem_u32(&sVh[srow]), qkvh + g + offv);
        cp16(smem_u32(&sVl[srow]), qkvl + g + offv);
    }
    cp_commit();
    asm volatile("cp.async.wait_group 0;\n" ::: "memory");
    __syncthreads();

    // ---- S = Q @ K^T (per warp: rows m0..m0+15, all 64 cols) ----
    const int m0 = warp * 16;
    float accS[8][4];
    #pragma unroll
    for (int j = 0; j < 8; j++)
        #pragma unroll
        for (int q = 0; q < 4; q++) accS[j][q] = 0.f;

    #pragma unroll
    for (int ks = 0; ks < 4; ks++) {
        uint32_t qh[4], ql[4];
        const int arow = m0 + (lane & 15);
        const int acol = ks * 16 + ((lane >> 4) << 3);
        ldsm_x4(qh, smem_u32(&sQh[arow * AS + acol]));
        ldsm_x4(ql, smem_u32(&sQl[arow * AS + acol]));
        const int brow0 = lane & 7;
        const int bcol = ks * 16 + ((lane >> 3) & 1) * 8;
        #pragma unroll
        for (int j = 0; j < 8; j++) {
            uint32_t kh[2], kl[2];
            ldsm_x2(kh, smem_u32(&sKh[(j * 8 + brow0) * AS + bcol]));
            ldsm_x2(kl, smem_u32(&sKl[(j * 8 + brow0) * AS + bcol]));
            mma_bf16(accS[j], qh, kh);
            mma_bf16(accS[j], qh, kl);
            mma_bf16(accS[j], ql, kh);
        }
    }

    // ---- causal softmax in registers ----
    const int r0 = m0 + (lane >> 2);
    const int r8 = r0 + 8;
    const float scale = 0.125f;
    float mx0 = -1e30f, mx1 = -1e30f;
    #pragma unroll
    for (int j = 0; j < 8; j++) {
        int c = j * 8 + (lane & 3) * 2;
        accS[j][0] = (c     <= r0) ? accS[j][0] * scale : -1e30f;
        accS[j][1] = (c + 1 <= r0) ? accS[j][1] * scale : -1e30f;
        accS[j][2] = (c     <= r8) ? accS[j][2] * scale : -1e30f;
        accS[j][3] = (c + 1 <= r8) ? accS[j][3] * scale : -1e30f;
        mx0 = fmaxf(mx0, fmaxf(accS[j][0], accS[j][1]));
        mx1 = fmaxf(mx1, fmaxf(accS[j][2], accS[j][3]));
    }
    mx0 = fmaxf(mx0, __shfl_xor_sync(0xFFFFFFFF, mx0, 1));
    mx0 = fmaxf(mx0, __shfl_xor_sync(0xFFFFFFFF, mx0, 2));
    mx1 = fmaxf(mx1, __shfl_xor_sync(0xFFFFFFFF, mx1, 1));
    mx1 = fmaxf(mx1, __shfl_xor_sync(0xFFFFFFFF, mx1, 2));
    float sum0 = 0.f, sum1 = 0.f;
    #pragma unroll
    for (int j = 0; j < 8; j++) {
        accS[j][0] = __expf(accS[j][0] - mx0);
        accS[j][1] = __expf(accS[j][1] - mx0);
        accS[j][2] = __expf(accS[j][2] - mx1);
        accS[j][3] = __expf(accS[j][3] - mx1);
        sum0 += accS[j][0] + accS[j][1];
        sum1 += accS[j][2] + accS[j][3];
    }
    sum0 += __shfl_xor_sync(0xFFFFFFFF, sum0, 1);
    sum0 += __shfl_xor_sync(0xFFFFFFFF, sum0, 2);
    sum1 += __shfl_xor_sync(0xFFFFFFFF, sum1, 1);
    sum1 += __shfl_xor_sync(0xFFFFFFFF, sum1, 2);
    const float inv0 = 1.f / sum0, inv1 = 1.f / sum1;
    #pragma unroll
    for (int j = 0; j < 8; j++) {
        accS[j][0] *= inv0; accS[j][1] *= inv0;
        accS[j][2] *= inv1; accS[j][3] *= inv1;
    }

    // ---- O = P @ V  (P C-frag -> A-frag repack; V via ldmatrix.trans) ----
    float accO[8][4];
    #pragma unroll
    for (int j = 0; j < 8; j++)
        #pragma unroll
        for (int q = 0; q < 4; q++) accO[j][q] = 0.f;

    #pragma unroll
    for (int ks = 0; ks < 4; ks++) {
        const int j0 = 2 * ks, j1 = 2 * ks + 1;
        uint32_t ph[4], pl[4];
        pack_hilo(accS[j0][0], accS[j0][1], ph[0], pl[0]);
        pack_hilo(accS[j0][2], accS[j0][3], ph[1], pl[1]);
        pack_hilo(accS[j1][0], accS[j1][1], ph[2], pl[2]);
        pack_hilo(accS[j1][2], accS[j1][3], ph[3], pl[3]);
        // V trans-load: lanes 0-7 -> rows s0..s0+7, lanes 8-15 -> s0+8..s0+15
        const int trow = ks * 16 + ((lane >> 3) & 1) * 8 + (lane & 7);
        #pragma unroll
        for (int n = 0; n < 8; n++) {
            uint32_t vh[2], vl[2];
            ldsm_x2_trans(vh, smem_u32(&sVh[trow * AS + n * 8]));
            ldsm_x2_trans(vl, smem_u32(&sVl[trow * AS + n * 8]));
            mma_bf16(accO[n], ph, vh);
            mma_bf16(accO[n], ph, vl);
            mma_bf16(accO[n], pl, vh);
        }
    }

    // ---- stage O in smem (overlay on K), then coalesced fp16 write ----
    __syncthreads();   // everyone done with sK reads
    #pragma unroll
    for (int j = 0; j < 8; j++) {
        int c = j * 8 + (lane & 3) * 2;
        sO[r0 * 68 + c]     = accO[j][0];
        sO[r0 * 68 + c + 1] = accO[j][1];
        sO[r8 * 68 + c]     = accO[j][2];
        sO[r8 * 68 + c + 1] = accO[j][3];
    }
    __syncthreads();

    for (int i = tid; i < 64 * 16; i += 128) {
        int t = i >> 4, j = i & 15;
        float4 a = *(float4*)&sO[t * 68 + 4 * j];
        __half2 H0, H1;
        H0.x = __float2half_rn(a.x); H0.y = __float2half_rn(a.y);
        H1.x = __float2half_rn(a.z); H1.y = __float2half_rn(a.w);
        uint2 hv; hv.x = *(uint32_t*)&H0; hv.y = *(uint32_t*)&H1;
        size_t off = (size_t)(b * NT + t) * NC + h * NHS + 4 * j;
        *(uint2*)&Oh[off] = hv;
    }
}

// ---------------- launch ----------------
extern "C" void kernel_launch(void* const* d_in, const int* in_sizes, int n_in,
                              void* d_out, int out_size) {
    const float* x    = (const float*)d_in[0];
    const float* Wqkv = (const float*)d_in[1];
    const float* Wp   = (const float*)d_in[2];
    const float* bp   = (const float*)d_in[3];
    float* out = (float*)d_out;

    void *pXh, *pWqh, *pWph, *pQh, *pQl, *pAh;
    cudaGetSymbolAddress(&pXh,  g_Xh);
    cudaGetSymbolAddress(&pWqh, g_Wqh);
    cudaGetSymbolAddress(&pWph, g_Wph);
    cudaGetSymbolAddress(&pQh,  g_qkvh);
    cudaGetSymbolAddress(&pQl,  g_qkvl);
    cudaGetSymbolAddress(&pAh,  g_Ah);

    int n4;
    n4 = MTOK * NC / 4;
    split1h_kernel<<<(n4 + 255) / 256, 256>>>(x, (__half*)pXh, n4);
    n4 = F3 * NC / 4;
    split1h_kernel<<<(n4 + 255) / 256, 256>>>(Wqkv, (__half*)pWqh, n4);
    n4 = NC * NC / 4;
    split1h_kernel<<<(n4 + 255) / 256, 256>>>(Wp, (__half*)pWph, n4);

    cudaFuncSetAttribute(gemm_fp16, cudaFuncAttributeMaxDynamicSharedMemorySize, GM_SMEM_BYTES);

    // qkv(hi/lo bf16) = X @ Wqkv^T : M=131072, N=1152, K=384
    gemm_fp16<<<dim3(F3 / BN, MTOK / BM), 256, GM_SMEM_BYTES>>>(
        (const __half*)pXh, (const __half*)pWqh,
        nullptr, (__nv_bfloat16*)pQh, (__nv_bfloat16*)pQl,
        nullptr, NC, F3, 1);

    cudaFuncSetAttribute(attn_tc_kernel, cudaFuncAttributeMaxDynamicSharedMemorySize, ATTN_SMEM);
    attn_tc_kernel<<<NB * NHN, 128, ATTN_SMEM>>>(
        (const __nv_bfloat16*)pQh, (const __nv_bfloat16*)pQl,
        (__half*)pAh);

    // out = Attn @ Wp^T + bp : M=131072, N=384, K=384
    gemm_fp16<<<dim3(NC / BN, MTOK / BM), 256, GM_SMEM_BYTES>>>(
        (const __half*)pAh, (const __half*)pWph,
        out, nullptr, nullptr,
        bp, NC, NC, 0);
}